// round 14
// baseline (speedup 1.0000x reference)
#include <cuda_runtime.h>
#include <cuda_bf16.h>

#define BB 32
#define TT 1024
#define AC 20
#define SE 16
#define HH 64
#define NH 4
#define HD 16
#define BT (BB*TT)
#define NPART 512   // stat-reduction partial blocks (qkv & outproj grids)

typedef unsigned int u32;
typedef unsigned long long ull;

// ---------------- scratch (__device__ globals; no allocation) ----------------
__device__ __align__(256) __nv_bfloat16 g_qb[BB*NH*TT*HD];  // pre-scaled by 0.25*log2e
__device__ __align__(256) __nv_bfloat16 g_kb[BB*NH*TT*HD];
__device__ __align__(256) __nv_bfloat16 g_vt[BB*NH*HD*TT];  // transposed: [bh][dim][token]
__device__ __align__(256) __nv_bfloat16 g_ctx[BB*NH*TT*HD]; // bf16
__device__ __align__(256) float g_enh[BT*AC];

__device__ float g_Cq[HH*SE], g_Ck[HH*AC], g_Cv[HH*AC];
__device__ float g_bq2[HH], g_bk2[HH], g_bv2[HH], g_bf[AC];
__device__ __align__(16) __nv_bfloat16 g_Wfb[24*72];        // bf16, zero-padded

__device__ float g_part_a[NPART*2*AC];
__device__ float g_part_e[NPART*2*AC];

// ---------------- packed helpers (sm_103a) ----------------
__device__ __forceinline__ ull pk2(float x, float y) {
    ull r; asm("mov.b64 %0, {%1,%2};" : "=l"(r) : "f"(x), "f"(y)); return r;
}
__device__ __forceinline__ void up2(ull v, float& x, float& y) {
    asm("mov.b64 {%0,%1}, %2;" : "=f"(x), "=f"(y) : "l"(v));
}
__device__ __forceinline__ ull fma2(ull a, ull b, ull c) {
    ull d; asm("fma.rn.f32x2 %0, %1, %2, %3;" : "=l"(d) : "l"(a), "l"(b), "l"(c)); return d;
}
__device__ __forceinline__ ull mul2(ull a, ull b) {
    ull d; asm("mul.rn.f32x2 %0, %1, %2;" : "=l"(d) : "l"(a), "l"(b)); return d;
}
__device__ __forceinline__ ull add2(ull a, ull b) {
    ull d; asm("add.rn.f32x2 %0, %1, %2;" : "=l"(d) : "l"(a), "l"(b)); return d;
}
__device__ __forceinline__ u32 cvt2bf(float hi, float lo) {
    u32 r; asm("cvt.rn.bf16x2.f32 %0, %1, %2;" : "=r"(r) : "f"(hi), "f"(lo)); return r;
}
__device__ __forceinline__ u32 bex2(u32 x) {
    u32 r; asm("ex2.approx.ftz.bf16x2 %0, %1;" : "=r"(r) : "r"(x)); return r;
}
__device__ __forceinline__ void ldsm4(u32& r0, u32& r1, u32& r2, u32& r3, u32 a) {
    asm volatile("ldmatrix.sync.aligned.m8n8.x4.shared.b16 {%0,%1,%2,%3}, [%4];"
        : "=r"(r0), "=r"(r1), "=r"(r2), "=r"(r3) : "r"(a));
}
__device__ __forceinline__ void mma16816(float* d,
    u32 a0, u32 a1, u32 a2, u32 a3, u32 b0, u32 b1,
    float c0, float c1, float c2, float c3) {
    asm("mma.sync.aligned.m16n8k16.row.col.f32.bf16.bf16.f32 "
        "{%0,%1,%2,%3}, {%4,%5,%6,%7}, {%8,%9}, {%10,%11,%12,%13};"
        : "=f"(d[0]), "=f"(d[1]), "=f"(d[2]), "=f"(d[3])
        : "r"(a0), "r"(a1), "r"(a2), "r"(a3), "r"(b0), "r"(b1),
          "f"(c0), "f"(c1), "f"(c2), "f"(c3));
}

// ---------------- K0: fuse linear layers (grid-stride) ----------------
__global__ void k_fuse(const float* __restrict__ Wq,  const float* __restrict__ bq,
                       const float* __restrict__ Wkv, const float* __restrict__ bkv,
                       const float* __restrict__ in_w, const float* __restrict__ in_b,
                       const float* __restrict__ out_w, const float* __restrict__ out_b,
                       const float* __restrict__ proj_w, const float* __restrict__ proj_b) {
    int g  = blockIdx.x * blockDim.x + threadIdx.x;
    int gs = gridDim.x * blockDim.x;
    for (int idx = g; idx < HH*SE; idx += gs) {
        int j = idx / SE, c = idx % SE;
        float acc = 0.f;
        #pragma unroll 8
        for (int i = 0; i < HH; i++) acc += in_w[j*HH+i] * Wq[i*SE+c];
        g_Cq[idx] = acc;
    }
    for (int idx = g; idx < HH*AC; idx += gs) {
        int j = idx / AC, c = idx % AC;
        float acc = 0.f;
        #pragma unroll 8
        for (int i = 0; i < HH; i++) acc += in_w[(HH+j)*HH+i] * Wkv[i*AC+c];
        g_Ck[idx] = acc;
    }
    for (int idx = g; idx < HH*AC; idx += gs) {
        int j = idx / AC, c = idx % AC;
        float acc = 0.f;
        #pragma unroll 8
        for (int i = 0; i < HH; i++) acc += in_w[(2*HH+j)*HH+i] * Wkv[(HH+i)*AC+c];
        g_Cv[idx] = acc;
    }
    for (int idx = g; idx < 24*72; idx += gs) {
        int r = idx / 72, c = idx % 72;
        float acc = 0.f;
        if (r < AC && c < HH) {
            #pragma unroll 8
            for (int j = 0; j < HH; j++) acc += proj_w[r*HH+j] * out_w[j*HH+c];
        }
        g_Wfb[idx] = __float2bfloat16(acc);
    }
    for (int j = g; j < HH; j += gs) {
        float aq = in_b[j], ak = in_b[HH+j], av = in_b[2*HH+j];
        #pragma unroll 8
        for (int i = 0; i < HH; i++) {
            aq += in_w[j*HH+i]        * bq[i];
            ak += in_w[(HH+j)*HH+i]   * bkv[i];
            av += in_w[(2*HH+j)*HH+i] * bkv[HH+i];
        }
        g_bq2[j] = aq; g_bk2[j] = ak; g_bv2[j] = av;
    }
    for (int c = g; c < AC; c += gs) {
        float acc = proj_b[c];
        #pragma unroll 8
        for (int j = 0; j < HH; j++) acc += proj_w[c*HH+j] * out_b[j];
        g_bf[c] = acc;
    }
}

// ---------------- K1: QKV projection, head-parallel (thread = token x head) ----------
// 64 tokens/block, 256 threads: tok = blk*64 + tid/4, head = tid%4
__global__ void __launch_bounds__(256) k_qkv(const float* __restrict__ semantic,
                                             const float* __restrict__ acoustic) {
    __shared__ __align__(16) float sW[HH*SE + 2*HH*AC];
    __shared__ float sB[3*HH];
    __shared__ float sred[2*AC];
    int tid = threadIdx.x;
    for (int i = tid; i < HH*SE; i += 256)        sW[i]            = g_Cq[i];
    for (int i = tid; i < HH*AC; i += 256)        sW[HH*SE+i]      = g_Ck[i];
    for (int i = tid; i < HH*AC; i += 256)        sW[HH*SE+HH*AC+i]= g_Cv[i];
    for (int i = tid; i < HH; i += 256) { sB[i] = g_bq2[i]; sB[HH+i] = g_bk2[i]; sB[2*HH+i] = g_bv2[i]; }
    if (tid < 2*AC) sred[tid] = 0.f;
    __syncthreads();

    int tok  = blockIdx.x * 64 + (tid >> 2);
    int h    = tid & 3;
    int lane = tid & 31;
    int b = tok >> 10, t = tok & 1023;

    float s[SE];
    {
        const float4* p = (const float4*)(semantic + (size_t)tok*SE);
        #pragma unroll
        for (int i = 0; i < 4; i++) { float4 v = p[i]; s[4*i]=v.x; s[4*i+1]=v.y; s[4*i+2]=v.z; s[4*i+3]=v.w; }
    }
    float a[AC];
    {
        const float4* p = (const float4*)(acoustic + (size_t)tok*AC);
        #pragma unroll
        for (int i = 0; i < 5; i++) { float4 v = p[i]; a[4*i]=v.x; a[4*i+1]=v.y; a[4*i+2]=v.z; a[4*i+3]=v.w; }
    }
    ull s2[8], a2[10];
    #pragma unroll
    for (int i = 0; i < 8; i++)  s2[i] = pk2(s[2*i], s[2*i+1]);
    #pragma unroll
    for (int i = 0; i < 10; i++) a2[i] = pk2(a[2*i], a[2*i+1]);

    const float SC = 0.25f * 1.4426950408889634f;

    float oq[HD], ok[HD], ov[HD];
    #pragma unroll
    for (int d = 0; d < HD; d++) {
        int j = h*HD + d;
        {
            const ull* w = (const ull*)&sW[j*SE];
            ull u0 = mul2(s2[0], w[0]);
            ull u1 = mul2(s2[1], w[1]);
            #pragma unroll
            for (int i = 2; i < 8; i += 2) {
                u0 = fma2(s2[i],   w[i],   u0);
                u1 = fma2(s2[i+1], w[i+1], u1);
            }
            float x, y; up2(add2(u0, u1), x, y);
            oq[d] = (x + y + sB[j]) * SC;
        }
        {
            const ull* wk = (const ull*)&sW[HH*SE + j*AC];
            const ull* wv = (const ull*)&sW[HH*SE + HH*AC + j*AC];
            ull k0 = mul2(a2[0], wk[0]);
            ull k1 = mul2(a2[1], wk[1]);
            ull v0 = mul2(a2[0], wv[0]);
            ull v1 = mul2(a2[1], wv[1]);
            #pragma unroll
            for (int i = 2; i < 10; i += 2) {
                k0 = fma2(a2[i],   wk[i],   k0);
                k1 = fma2(a2[i+1], wk[i+1], k1);
                v0 = fma2(a2[i],   wv[i],   v0);
                v1 = fma2(a2[i+1], wv[i+1], v1);
            }
            float x, y; up2(add2(k0, k1), x, y);
            ok[d] = x + y + sB[HH+j];
            up2(add2(v0, v1), x, y);
            ov[d] = x + y + sB[2*HH+j];
        }
    }

    size_t rbase = ((size_t)(b*NH + h) * TT + t) * HD;
    {
        u32 qp[8], kp[8];
        #pragma unroll
        for (int i = 0; i < 8; i++) {
            qp[i] = cvt2bf(oq[2*i+1], oq[2*i]);
            kp[i] = cvt2bf(ok[2*i+1], ok[2*i]);
        }
        uint4* dq = (uint4*)(g_qb + rbase);
        uint4* dk = (uint4*)(g_kb + rbase);
        dq[0] = make_uint4(qp[0], qp[1], qp[2], qp[3]);
        dq[1] = make_uint4(qp[4], qp[5], qp[6], qp[7]);
        dk[0] = make_uint4(kp[0], kp[1], kp[2], kp[3]);
        dk[1] = make_uint4(kp[4], kp[5], kp[6], kp[7]);
    }
    {
        size_t vbase = ((size_t)(b*NH + h) * HD) * TT + t;
        #pragma unroll
        for (int d = 0; d < HD; d++)
            g_vt[vbase + (size_t)d*TT] = __float2bfloat16(ov[d]);
    }

    // acoustic stats: thread's head index picks its 5-channel group
    #pragma unroll
    for (int i = 0; i < 5; i++) {
        int c = h*5 + i;
        float v = a[c];
        float vv = v * v;
        #pragma unroll
        for (int off = 4; off <= 16; off <<= 1) {
            v  += __shfl_xor_sync(0xffffffffu, v,  off);
            vv += __shfl_xor_sync(0xffffffffu, vv, off);
        }
        if (lane < 4) {  // lane 0..3 holds the sum for head group = lane
            atomicAdd(&sred[c],      v);
            atomicAdd(&sred[AC + c], vv);
        }
    }
    __syncthreads();
    if (tid < 2*AC) g_part_a[blockIdx.x*2*AC + tid] = sred[tid];
}

// ---------------- K2: flash attention (ldmatrix + double-buffered tiles) ----------
#define KSTR 24
#define VSTR 136
#define KBUF (128*KSTR)
#define VBUF (HD*VSTR)
__global__ void __launch_bounds__(256) k_attn() {
    __shared__ __align__(16) __nv_bfloat16 sK[2*KBUF];
    __shared__ __align__(16) __nv_bfloat16 sVt[2*VBUF];

    int tid  = threadIdx.x;
    int lane = tid & 31, w = tid >> 5;
    int bh   = blockIdx.z * NH + blockIdx.y;
    const __nv_bfloat16* Qg = g_qb + (size_t)bh * TT * HD;
    const __nv_bfloat16* Kg = g_kb + (size_t)bh * TT * HD;
    const __nv_bfloat16* Vg = g_vt + (size_t)bh * HD * TT;

    int qbase = blockIdx.x * 128 + w * 16;
    int rq    = lane >> 2;
    int colq  = (lane & 3) * 2;

    u32 qa0 = *(const u32*)(Qg + (size_t)(qbase + rq    ) * HD + colq);
    u32 qa1 = *(const u32*)(Qg + (size_t)(qbase + rq + 8) * HD + colq);
    u32 qa2 = *(const u32*)(Qg + (size_t)(qbase + rq    ) * HD + colq + 8);
    u32 qa3 = *(const u32*)(Qg + (size_t)(qbase + rq + 8) * HD + colq + 8);

    float o0[4] = {0.f,0.f,0.f,0.f};
    float o1[4] = {0.f,0.f,0.f,0.f};
    float lac[4] = {0.f,0.f,0.f,0.f};
    const u32 ONE2 = 0x3F803F80u;

    int krow = tid >> 1, kseg = tid & 1;
    int vrow = tid >> 4, vseg = tid & 15;
    const __nv_bfloat16* kgp = Kg + (size_t)krow * HD + kseg*8;
    const __nv_bfloat16* vgp = Vg + (size_t)vrow * TT + vseg*8;
    int kst = krow*KSTR + kseg*8;
    int vst = vrow*VSTR + vseg*8;

    {
        uint4 kv = *(const uint4*)kgp;
        uint4 vv = *(const uint4*)vgp;
        *(uint4*)(sK  + kst) = kv;
        *(uint4*)(sVt + vst) = vv;
    }
    __syncthreads();

    u32 sKu = (u32)__cvta_generic_to_shared(sK);
    u32 sVu = (u32)__cvta_generic_to_shared(sVt);
    int lmrow = (lane & 7) + ((lane >> 4) << 3);
    int lmhi  = (lane >> 3) & 1;
    int lm_k = lmrow * (KSTR*2) + lmhi * 16;
    int lm_v = lmrow * (VSTR*2) + lmhi * 16;

    for (int kc = 0; kc < 8; kc++) {
        int cur = kc & 1;
        uint4 kvn, vvn;
        if (kc < 7) {
            kvn = *(const uint4*)(kgp + (size_t)(kc+1)*128*HD);
            vvn = *(const uint4*)(vgp + (kc+1)*128);
        }

        u32 ka = sKu + cur*(KBUF*2) + lm_k;
        u32 va = sVu + cur*(VBUF*2) + lm_v;
        #pragma unroll
        for (int sub = 0; sub < 8; sub++) {
            u32 kb0, kb1, kb2, kb3;
            ldsm4(kb0, kb1, kb2, kb3, ka);  ka += 16*(KSTR*2);
            u32 vb0, vb1, vb2, vb3;
            ldsm4(vb0, vb1, vb2, vb3, va);  va += 32;

            float s0[4], s1[4];
            mma16816(s0, qa0,qa1,qa2,qa3, kb0,kb1, 0.f,0.f,0.f,0.f);
            mma16816(s1, qa0,qa1,qa2,qa3, kb2,kb3, 0.f,0.f,0.f,0.f);

            u32 pa0 = bex2(cvt2bf(s0[1], s0[0]));
            u32 pa1 = bex2(cvt2bf(s0[3], s0[2]));
            u32 pa2 = bex2(cvt2bf(s1[1], s1[0]));
            u32 pa3 = bex2(cvt2bf(s1[3], s1[2]));

            mma16816(o0, pa0,pa1,pa2,pa3, vb0,vb1, o0[0],o0[1],o0[2],o0[3]);
            mma16816(o1, pa0,pa1,pa2,pa3, vb2,vb3, o1[0],o1[1],o1[2],o1[3]);
            mma16816(lac, pa0,pa1,pa2,pa3, ONE2, ONE2, lac[0],lac[1],lac[2],lac[3]);
        }

        if (kc < 7) {
            int nb = (kc+1) & 1;
            *(uint4*)(sK  + nb*KBUF + kst) = kvn;
            *(uint4*)(sVt + nb*VBUF + vst) = vvn;
        }
        __syncthreads();
    }

    float ri_lo = 1.0f / lac[0], ri_hi = 1.0f / lac[2];

    __nv_bfloat16* Og = g_ctx + (size_t)bh * TT * HD;
    int rlo = qbase + rq;
    *(u32*)(Og + (size_t)rlo*HD + colq)         = cvt2bf(o0[1]*ri_lo, o0[0]*ri_lo);
    *(u32*)(Og + (size_t)rlo*HD + colq + 8)     = cvt2bf(o1[1]*ri_lo, o1[0]*ri_lo);
    *(u32*)(Og + (size_t)(rlo+8)*HD + colq)     = cvt2bf(o0[3]*ri_hi, o0[2]*ri_hi);
    *(u32*)(Og + (size_t)(rlo+8)*HD + colq + 8) = cvt2bf(o1[3]*ri_hi, o1[2]*ri_hi);
}

// ---------------- K3: MMA output projection, 64-token tiles ----------
__global__ void __launch_bounds__(128) k_outproj(const float* __restrict__ acoustic,
                                                 const float* __restrict__ residual_logit,
                                                 float* __restrict__ out,
                                                 const float* __restrict__ gamma,
                                                 const float* __restrict__ beta) {
    __shared__ __align__(16) __nv_bfloat16 sCtx[64*72];
    __shared__ __align__(16) __nv_bfloat16 sWf[24*72];
    __shared__ __align__(16) float sAc[64*AC];
    __shared__ float sbf[AC], sG[AC], sBt[AC];
    __shared__ float sred[2*AC];
    int tid = threadIdx.x;

    for (int i = tid; i < 216; i += 128)
        ((uint4*)sWf)[i] = ((const uint4*)g_Wfb)[i];
    if (tid < AC) { sbf[tid] = g_bf[tid]; sG[tid] = gamma[tid]; sBt[tid] = beta[tid]; }
    if (tid < 2*AC) sred[tid] = 0.f;

    int tile0 = blockIdx.x * 64;
    int b = tile0 >> 10, t0 = tile0 & 1023;
    {
        int row = tid >> 1, seg = tid & 1;    // 64 rows x 2 segs = 128 threads
        #pragma unroll
        for (int h = 0; h < NH; h++) {
            const uint4* src = (const uint4*)(g_ctx + ((size_t)(b*NH+h)*TT + t0) * HD);
            *(uint4*)&sCtx[row*72 + h*16 + seg*8] = src[row*2 + seg];
        }
    }
    {
        const uint4* src = (const uint4*)(acoustic + (size_t)tile0 * AC);
        #pragma unroll
        for (int r = 0; r < 3; r++) {
            int i = r*128 + tid;
            if (i < 320) ((uint4*)sAc)[i] = src[i];
        }
    }
    __syncthreads();

    int lane = tid & 31, w = tid >> 5;         // 4 warps
    int rq = lane >> 2, colq = (lane & 3) * 2;
    int r0 = w*16 + rq;

    float d0[4] = {0,0,0,0}, d1[4] = {0,0,0,0}, d2[4] = {0,0,0,0};
    #pragma unroll
    for (int kk = 0; kk < 4; kk++) {
        const __nv_bfloat16* acol = sCtx + kk*16 + colq;
        u32 a0 = *(const u32*)(acol + (size_t)r0*72);
        u32 a1 = *(const u32*)(acol + (size_t)(r0+8)*72);
        u32 a2 = *(const u32*)(acol + (size_t)r0*72 + 8);
        u32 a3 = *(const u32*)(acol + (size_t)(r0+8)*72 + 8);
        const __nv_bfloat16* bcol = sWf + kk*16 + colq;
        u32 b00 = *(const u32*)(bcol + (size_t)rq*72);
        u32 b01 = *(const u32*)(bcol + (size_t)rq*72 + 8);
        u32 b10 = *(const u32*)(bcol + (size_t)(8+rq)*72);
        u32 b11 = *(const u32*)(bcol + (size_t)(8+rq)*72 + 8);
        u32 b20 = *(const u32*)(bcol + (size_t)(16+rq)*72);
        u32 b21 = *(const u32*)(bcol + (size_t)(16+rq)*72 + 8);
        mma16816(d0, a0,a1,a2,a3, b00,b01, d0[0],d0[1],d0[2],d0[3]);
        mma16816(d1, a0,a1,a2,a3, b10,b11, d1[0],d1[1],d1[2],d1[3]);
        mma16816(d2, a0,a1,a2,a3, b20,b21, d2[0],d2[1],d2[2],d2[3]);
    }

    float sig = 1.0f / (1.0f + __expf(-__ldg(residual_logit)));

    float eA[6], eB[6];
    float sumA = 0.f, sumB = 0.f;
    #pragma unroll
    for (int nt = 0; nt < 3; nt++) {
        float* dd = (nt==0) ? d0 : ((nt==1) ? d1 : d2);
        #pragma unroll
        for (int j = 0; j < 2; j++) {
            int c = nt*8 + colq + j;
            float ea = 0.f, eb = 0.f;
            if (c < AC) {
                ea = sAc[r0*AC + c]     + sig * (dd[j]   + sbf[c]);
                eb = sAc[(r0+8)*AC + c] + sig * (dd[2+j] + sbf[c]);
                sumA += ea; sumB += eb;
            }
            eA[nt*2+j] = ea; eB[nt*2+j] = eb;
        }
    }

    #pragma unroll
    for (int q = 0; q < 6; q++) {
        int c = (q>>1)*8 + colq + (q&1);
        float v  = eA[q] + eB[q];
        float vv = eA[q]*eA[q] + eB[q]*eB[q];
        v  += __shfl_xor_sync(0xffffffffu, v,  4);  vv += __shfl_xor_sync(0xffffffffu, vv, 4);
        v  += __shfl_xor_sync(0xffffffffu, v,  8);  vv += __shfl_xor_sync(0xffffffffu, vv, 8);
        v  += __shfl_xor_sync(0xffffffffu, v, 16);  vv += __shfl_xor_sync(0xffffffffu, vv, 16);
        if (lane < 4 && c < AC) {
            atomicAdd(&sred[c],      v);
            atomicAdd(&sred[AC + c], vv);
        }
    }

    float muA = sumA, muB = sumB;
    muA += __shfl_xor_sync(0xffffffffu, muA, 1); muA += __shfl_xor_sync(0xffffffffu, muA, 2);
    muB += __shfl_xor_sync(0xffffffffu, muB, 1); muB += __shfl_xor_sync(0xffffffffu, muB, 2);
    muA *= (1.0f/AC); muB *= (1.0f/AC);
    float varA = 0.f, varB = 0.f;
    #pragma unroll
    for (int q = 0; q < 6; q++) {
        int c = (q>>1)*8 + colq + (q&1);
        if (c < AC) {
            float dA = eA[q] - muA; varA += dA*dA;
            float dB = eB[q] - muB; varB += dB*dB;
        }
    }
    varA += __shfl_xor_sync(0xffffffffu, varA, 1); varA += __shfl_xor_sync(0xffffffffu, varA, 2);
    varB += __shfl_xor_sync(0xffffffffu, varB, 1); varB += __shfl_xor_sync(0xffffffffu, varB, 2);
    float rA = rsqrtf(varA*(1.0f/AC) + 1e-5f);
    float rB = rsqrtf(varB*(1.0f/AC) + 1e-5f);

    size_t tokA = (size_t)(tile0 + r0) * AC;
    size_t tokB = tokA + 8*AC;
    #pragma unroll
    for (int nt = 0; nt < 3; nt++) {
        int c = nt*8 + colq;
        if (c + 1 < AC) {
            float gA0 = sG[c], gA1 = sG[c+1], bb0 = sBt[c], bb1 = sBt[c+1];
            *(float2*)(out + tokA + c) = make_float2((eA[nt*2]-muA)*rA*gA0 + bb0,
                                                     (eA[nt*2+1]-muA)*rA*gA1 + bb1);
            *(float2*)(out + tokB + c) = make_float2((eB[nt*2]-muB)*rB*gA0 + bb0,
                                                     (eB[nt*2+1]-muB)*rB*gA1 + bb1);
            *(float2*)(g_enh + tokA + c) = make_float2(eA[nt*2], eA[nt*2+1]);
            *(float2*)(g_enh + tokB + c) = make_float2(eB[nt*2], eB[nt*2+1]);
        }
    }

    __syncthreads();
    if (tid < 2*AC) g_part_e[blockIdx.x*2*AC + tid] = sred[tid];
}

// ---------------- K4: merged stats-check + fixup (per-block redundant fp32 stats) ----
__global__ void __launch_bounds__(256) k_fixln(float* __restrict__ out,
                                               const float* __restrict__ gamma,
                                               const float* __restrict__ beta) {
    __shared__ float sA[160];
    __shared__ float sE[160];
    __shared__ float s_corr[AC], s_add[AC];
    __shared__ int sflag;
    int tid = threadIdx.x;
    if (tid == 0) sflag = 0;

    if (tid < 160) {
        int idx = tid % 40;
        int q   = tid / 40;
        const float* pa = g_part_a + idx;
        const float* pe = g_part_e + idx;
        int i0 = q * (NPART/4);
        float a0 = 0.f, a1 = 0.f, e0 = 0.f, e1 = 0.f;
        #pragma unroll 4
        for (int i = 0; i < NPART/4; i += 2) {
            a0 += pa[(size_t)(i0 + i)     * 2*AC];
            a1 += pa[(size_t)(i0 + i + 1) * 2*AC];
            e0 += pe[(size_t)(i0 + i)     * 2*AC];
            e1 += pe[(size_t)(i0 + i + 1) * 2*AC];
        }
        sA[tid] = a0 + a1;
        sE[tid] = e0 + e1;
    }
    __syncthreads();

    if (tid < AC) {
        int c = tid;
        float sa = (sA[c]    + sA[40+c])    + (sA[80+c]    + sA[120+c]);
        float qa = (sA[AC+c] + sA[40+AC+c]) + (sA[80+AC+c] + sA[120+AC+c]);
        float se = (sE[c]    + sE[40+c])    + (sE[80+c]    + sE[120+c]);
        float qe = (sE[AC+c] + sE[40+AC+c]) + (sE[80+AC+c] + sE[120+AC+c]);
        const float N = (float)BT;
        float mean = sa / N;
        float va = (qa - sa*sa/N) / (N - 1.0f); if (va < 0.f) va = 0.f;
        float sda = sqrtf(va);
        float ostd = sda + 1e-8f;
        float ve = (qe - se*se/N) / (N - 1.0f); if (ve < 0.f) ve = 0.f;
        float sde = sqrtf(ve);
        float ratio = (sde / ostd) / ((sda / ostd) + 1e-8f);
        float corr = (ratio < 0.4f) ? (0.4f / ratio) : 1.0f;
        s_corr[c] = corr;
        s_add[c]  = mean * (1.0f - corr);
        if (corr != 1.0f) atomicOr(&sflag, 1);
    }
    __syncthreads();
    if (sflag == 0) return;   // speculative LN already correct

    int token = blockIdx.x * 128 + (tid >> 1);
    int cb = (tid & 1) * 10;

    float f[10];
    {
        const float2* p = (const float2*)(g_enh + (size_t)token*AC + cb);
        #pragma unroll
        for (int i = 0; i < 5; i++) { float2 v = p[i]; f[2*i] = v.x; f[2*i+1] = v.y; }
    }
    float mu = 0.f;
    #pragma unroll
    for (int ci = 0; ci < 10; ci++) {
        f[ci] = f[ci] * s_corr[cb+ci] + s_add[cb+ci];
        mu += f[ci];
    }
    mu += __shfl_xor_sync(0xffffffffu, mu, 1);
    mu *= (1.0f / AC);
    float var = 0.f;
    #pragma unroll
    for (int ci = 0; ci < 10; ci++) { float d = f[ci] - mu; var += d * d; }
    var += __shfl_xor_sync(0xffffffffu, var, 1);
    var *= (1.0f / AC);
    float r = rsqrtf(var + 1e-5f);

    float o[10];
    #pragma unroll
    for (int ci = 0; ci < 10; ci++)
        o[ci] = (f[ci] - mu) * r * __ldg(&gamma[cb+ci]) + __ldg(&beta[cb+ci]);
    float2* dst = (float2*)(out + (size_t)token*AC + cb);
    #pragma unroll
    for (int i = 0; i < 5; i++) dst[i] = make_float2(o[2*i], o[2*i+1]);
}

// ---------------- launcher ----------------
extern "C" void kernel_launch(void* const* d_in, const int* in_sizes, int n_in,
                              void* d_out, int out_size) {
    (void)in_sizes; (void)n_in; (void)out_size;
    const float* acoustic = (const float*)d_in[0];
    const float* semantic = (const float*)d_in[1];
    const float* Wq       = (const float*)d_in[2];
    const float* bq       = (const float*)d_in[3];
    const float* Wkv      = (const float*)d_in[4];
    const float* bkv      = (const float*)d_in[5];
    const float* in_w     = (const float*)d_in[6];
    const float* in_b     = (const float*)d_in[7];
    const float* out_w    = (const float*)d_in[8];
    const float* out_b    = (const float*)d_in[9];
    const float* proj_w   = (const float*)d_in[10];
    const float* proj_b   = (const float*)d_in[11];
    const float* rl       = (const float*)d_in[12];
    const float* gamma    = (const float*)d_in[13];
    const float* beta     = (const float*)d_in[14];
    float* out = (float*)d_out;

    k_fuse<<<64, 128>>>(Wq, bq, Wkv, bkv, in_w, in_b, out_w, out_b, proj_w, proj_b);
    k_qkv<<<NPART, 256>>>(semantic, acoustic);                 // launch 1 (512 blocks)
    dim3 ga(TT/128, NH, BB);
    k_attn<<<ga, 256>>>();                                     // launch 2
    k_outproj<<<NPART, 128>>>(acoustic, rl, out, gamma, beta); // launch 3 <- captured
    k_fixln<<<256, 256>>>(out, gamma, beta);                   // launch 4
}

// round 16
// speedup vs baseline: 1.5907x; 1.5907x over previous
#include <cuda_runtime.h>
#include <cuda_bf16.h>

#define BB 32
#define TT 1024
#define AC 20
#define SE 16
#define HH 64
#define NH 4
#define HD 16
#define BT (BB*TT)
#define NRED 256   // stat-reduction partial blocks

typedef unsigned int u32;
typedef unsigned long long ull;

// ---------------- scratch (__device__ globals; no allocation) ----------------
__device__ __align__(256) __nv_bfloat16 g_qb[BB*NH*TT*HD];  // pre-scaled by 0.25*log2e
__device__ __align__(256) __nv_bfloat16 g_kb[BB*NH*TT*HD];
__device__ __align__(256) __nv_bfloat16 g_vt[BB*NH*HD*TT];  // transposed: [bh][dim][token]
__device__ __align__(256) __nv_bfloat16 g_ctx[BB*NH*TT*HD]; // bf16
__device__ __align__(256) float g_enh[BT*AC];

__device__ float g_Cq[HH*SE], g_Ck[HH*AC], g_Cv[HH*AC];
__device__ float g_bq2[HH], g_bk2[HH], g_bv2[HH], g_bf[AC];
__device__ __align__(16) __nv_bfloat16 g_Wfb[24*72];        // bf16, zero-padded

__device__ float g_part_a[NRED*2*AC];
__device__ float g_part_e[NRED*2*AC];

// ---------------- packed helpers (sm_103a) ----------------
__device__ __forceinline__ ull pk2(float x, float y) {
    ull r; asm("mov.b64 %0, {%1,%2};" : "=l"(r) : "f"(x), "f"(y)); return r;
}
__device__ __forceinline__ void up2(ull v, float& x, float& y) {
    asm("mov.b64 {%0,%1}, %2;" : "=f"(x), "=f"(y) : "l"(v));
}
__device__ __forceinline__ ull fma2(ull a, ull b, ull c) {
    ull d; asm("fma.rn.f32x2 %0, %1, %2, %3;" : "=l"(d) : "l"(a), "l"(b), "l"(c)); return d;
}
__device__ __forceinline__ ull mul2(ull a, ull b) {
    ull d; asm("mul.rn.f32x2 %0, %1, %2;" : "=l"(d) : "l"(a), "l"(b)); return d;
}
__device__ __forceinline__ ull add2(ull a, ull b) {
    ull d; asm("add.rn.f32x2 %0, %1, %2;" : "=l"(d) : "l"(a), "l"(b)); return d;
}
__device__ __forceinline__ u32 cvt2bf(float hi, float lo) {
    u32 r; asm("cvt.rn.bf16x2.f32 %0, %1, %2;" : "=r"(r) : "f"(hi), "f"(lo)); return r;
}
__device__ __forceinline__ u32 bex2(u32 x) {
    u32 r; asm("ex2.approx.ftz.bf16x2 %0, %1;" : "=r"(r) : "r"(x)); return r;
}
__device__ __forceinline__ void ldsm4(u32& r0, u32& r1, u32& r2, u32& r3, u32 a) {
    asm volatile("ldmatrix.sync.aligned.m8n8.x4.shared.b16 {%0,%1,%2,%3}, [%4];"
        : "=r"(r0), "=r"(r1), "=r"(r2), "=r"(r3) : "r"(a));
}
__device__ __forceinline__ void mma16816(float* d,
    u32 a0, u32 a1, u32 a2, u32 a3, u32 b0, u32 b1,
    float c0, float c1, float c2, float c3) {
    asm("mma.sync.aligned.m16n8k16.row.col.f32.bf16.bf16.f32 "
        "{%0,%1,%2,%3}, {%4,%5,%6,%7}, {%8,%9}, {%10,%11,%12,%13};"
        : "=f"(d[0]), "=f"(d[1]), "=f"(d[2]), "=f"(d[3])
        : "r"(a0), "r"(a1), "r"(a2), "r"(a3), "r"(b0), "r"(b1),
          "f"(c0), "f"(c1), "f"(c2), "f"(c3));
}

// ---------------- K0: fuse linear layers (grid-stride) ----------------
__global__ void k_fuse(const float* __restrict__ Wq,  const float* __restrict__ bq,
                       const float* __restrict__ Wkv, const float* __restrict__ bkv,
                       const float* __restrict__ in_w, const float* __restrict__ in_b,
                       const float* __restrict__ out_w, const float* __restrict__ out_b,
                       const float* __restrict__ proj_w, const float* __restrict__ proj_b) {
    int g  = blockIdx.x * blockDim.x + threadIdx.x;
    int gs = gridDim.x * blockDim.x;
    for (int idx = g; idx < HH*SE; idx += gs) {
        int j = idx / SE, c = idx % SE;
        float acc = 0.f;
        #pragma unroll 8
        for (int i = 0; i < HH; i++) acc += in_w[j*HH+i] * Wq[i*SE+c];
        g_Cq[idx] = acc;
    }
    for (int idx = g; idx < HH*AC; idx += gs) {
        int j = idx / AC, c = idx % AC;
        float acc = 0.f;
        #pragma unroll 8
        for (int i = 0; i < HH; i++) acc += in_w[(HH+j)*HH+i] * Wkv[i*AC+c];
        g_Ck[idx] = acc;
    }
    for (int idx = g; idx < HH*AC; idx += gs) {
        int j = idx / AC, c = idx % AC;
        float acc = 0.f;
        #pragma unroll 8
        for (int i = 0; i < HH; i++) acc += in_w[(2*HH+j)*HH+i] * Wkv[(HH+i)*AC+c];
        g_Cv[idx] = acc;
    }
    for (int idx = g; idx < 24*72; idx += gs) {
        int r = idx / 72, c = idx % 72;
        float acc = 0.f;
        if (r < AC && c < HH) {
            #pragma unroll 8
            for (int j = 0; j < HH; j++) acc += proj_w[r*HH+j] * out_w[j*HH+c];
        }
        g_Wfb[idx] = __float2bfloat16(acc);
    }
    for (int j = g; j < HH; j += gs) {
        float aq = in_b[j], ak = in_b[HH+j], av = in_b[2*HH+j];
        #pragma unroll 8
        for (int i = 0; i < HH; i++) {
            aq += in_w[j*HH+i]        * bq[i];
            ak += in_w[(HH+j)*HH+i]   * bkv[i];
            av += in_w[(2*HH+j)*HH+i] * bkv[HH+i];
        }
        g_bq2[j] = aq; g_bk2[j] = ak; g_bv2[j] = av;
    }
    for (int c = g; c < AC; c += gs) {
        float acc = proj_b[c];
        #pragma unroll 8
        for (int j = 0; j < HH; j++) acc += proj_w[c*HH+j] * out_b[j];
        g_bf[c] = acc;
    }
}

// ---------------- K1: fused QKV projection (bf16 out, V transposed) + acoustic stats ----
__global__ void __launch_bounds__(128) k_qkv(const float* __restrict__ semantic,
                                             const float* __restrict__ acoustic) {
    __shared__ __align__(16) float sW[HH*SE + 2*HH*AC];
    __shared__ float sB[3*HH];
    int tid = threadIdx.x;
    for (int i = tid; i < HH*SE; i += 128)        sW[i]            = g_Cq[i];
    for (int i = tid; i < HH*AC; i += 128)        sW[HH*SE+i]      = g_Ck[i];
    for (int i = tid; i < HH*AC; i += 128)        sW[HH*SE+HH*AC+i]= g_Cv[i];
    for (int i = tid; i < HH; i += 128) { sB[i] = g_bq2[i]; sB[HH+i] = g_bk2[i]; sB[2*HH+i] = g_bv2[i]; }
    __syncthreads();

    int token = blockIdx.x * 128 + tid;
    int b = token >> 10, t = token & 1023;

    float s[SE];
    {
        const float4* p = (const float4*)(semantic + (size_t)token*SE);
        #pragma unroll
        for (int i = 0; i < 4; i++) { float4 v = p[i]; s[4*i]=v.x; s[4*i+1]=v.y; s[4*i+2]=v.z; s[4*i+3]=v.w; }
    }
    float a[AC];
    {
        const float4* p = (const float4*)(acoustic + (size_t)token*AC);
        #pragma unroll
        for (int i = 0; i < 5; i++) { float4 v = p[i]; a[4*i]=v.x; a[4*i+1]=v.y; a[4*i+2]=v.z; a[4*i+3]=v.w; }
    }
    ull s2[8], a2[10];
    #pragma unroll
    for (int i = 0; i < 8; i++)  s2[i] = pk2(s[2*i], s[2*i+1]);
    #pragma unroll
    for (int i = 0; i < 10; i++) a2[i] = pk2(a[2*i], a[2*i+1]);

    const float SC = 0.25f * 1.4426950408889634f;

    #pragma unroll
    for (int h = 0; h < NH; h++) {
        float oq[HD], ok[HD], ov[HD];
        #pragma unroll
        for (int d = 0; d < HD; d++) {
            int j = h*HD + d;
            {
                const ull* w = (const ull*)&sW[j*SE];
                ull u0 = mul2(s2[0], w[0]);
                ull u1 = mul2(s2[1], w[1]);
                #pragma unroll
                for (int i = 2; i < 8; i += 2) {
                    u0 = fma2(s2[i],   w[i],   u0);
                    u1 = fma2(s2[i+1], w[i+1], u1);
                }
                float x, y; up2(add2(u0, u1), x, y);
                oq[d] = (x + y + sB[j]) * SC;
            }
            {
                const ull* wk = (const ull*)&sW[HH*SE + j*AC];
                const ull* wv = (const ull*)&sW[HH*SE + HH*AC + j*AC];
                ull k0 = mul2(a2[0], wk[0]);
                ull k1 = mul2(a2[1], wk[1]);
                ull v0 = mul2(a2[0], wv[0]);
                ull v1 = mul2(a2[1], wv[1]);
                #pragma unroll
                for (int i = 2; i < 10; i += 2) {
                    k0 = fma2(a2[i],   wk[i],   k0);
                    k1 = fma2(a2[i+1], wk[i+1], k1);
                    v0 = fma2(a2[i],   wv[i],   v0);
                    v1 = fma2(a2[i+1], wv[i+1], v1);
                }
                float x, y; up2(add2(k0, k1), x, y);
                ok[d] = x + y + sB[HH+j];
                up2(add2(v0, v1), x, y);
                ov[d] = x + y + sB[2*HH+j];
            }
        }
        size_t rbase = ((size_t)(b*NH + h) * TT + t) * HD;
        {
            u32 qp[8], kp[8];
            #pragma unroll
            for (int i = 0; i < 8; i++) {
                qp[i] = cvt2bf(oq[2*i+1], oq[2*i]);
                kp[i] = cvt2bf(ok[2*i+1], ok[2*i]);
            }
            uint4* dq = (uint4*)(g_qb + rbase);
            uint4* dk = (uint4*)(g_kb + rbase);
            dq[0] = make_uint4(qp[0], qp[1], qp[2], qp[3]);
            dq[1] = make_uint4(qp[4], qp[5], qp[6], qp[7]);
            dk[0] = make_uint4(kp[0], kp[1], kp[2], kp[3]);
            dk[1] = make_uint4(kp[4], kp[5], kp[6], kp[7]);
        }
        {
            size_t vbase = ((size_t)(b*NH + h) * HD) * TT + t;
            #pragma unroll
            for (int d = 0; d < HD; d++)
                g_vt[vbase + (size_t)d*TT] = __float2bfloat16(ov[d]);
        }
    }

    __shared__ float sred[2*AC];
    if (tid < 2*AC) sred[tid] = 0.f;
    __syncthreads();
    #pragma unroll
    for (int c = 0; c < AC; c++) {
        float v = a[c];
        float vv = v * v;
        #pragma unroll
        for (int off = 16; off; off >>= 1) {
            v  += __shfl_xor_sync(0xffffffffu, v,  off);
            vv += __shfl_xor_sync(0xffffffffu, vv, off);
        }
        if ((tid & 31) == 0) {
            atomicAdd(&sred[c],      v);
            atomicAdd(&sred[AC + c], vv);
        }
    }
    __syncthreads();
    if (tid < 2*AC) g_part_a[blockIdx.x*2*AC + tid] = sred[tid];
}

// ---------------- K2: flash attention (ldmatrix + double-buffered tiles) ----------
#define KSTR 24
#define VSTR 136
#define KBUF (128*KSTR)
#define VBUF (HD*VSTR)
__global__ void __launch_bounds__(256) k_attn() {
    __shared__ __align__(16) __nv_bfloat16 sK[2*KBUF];
    __shared__ __align__(16) __nv_bfloat16 sVt[2*VBUF];

    int tid  = threadIdx.x;
    int lane = tid & 31, w = tid >> 5;
    int bh   = blockIdx.z * NH + blockIdx.y;
    const __nv_bfloat16* Qg = g_qb + (size_t)bh * TT * HD;
    const __nv_bfloat16* Kg = g_kb + (size_t)bh * TT * HD;
    const __nv_bfloat16* Vg = g_vt + (size_t)bh * HD * TT;

    int qbase = blockIdx.x * 128 + w * 16;
    int rq    = lane >> 2;
    int colq  = (lane & 3) * 2;

    u32 qa0 = *(const u32*)(Qg + (size_t)(qbase + rq    ) * HD + colq);
    u32 qa1 = *(const u32*)(Qg + (size_t)(qbase + rq + 8) * HD + colq);
    u32 qa2 = *(const u32*)(Qg + (size_t)(qbase + rq    ) * HD + colq + 8);
    u32 qa3 = *(const u32*)(Qg + (size_t)(qbase + rq + 8) * HD + colq + 8);

    float o0[4] = {0.f,0.f,0.f,0.f};
    float o1[4] = {0.f,0.f,0.f,0.f};
    float lac[4] = {0.f,0.f,0.f,0.f};
    const u32 ONE2 = 0x3F803F80u;

    int krow = tid >> 1, kseg = tid & 1;
    int vrow = tid >> 4, vseg = tid & 15;
    const __nv_bfloat16* kgp = Kg + (size_t)krow * HD + kseg*8;
    const __nv_bfloat16* vgp = Vg + (size_t)vrow * TT + vseg*8;
    int kst = krow*KSTR + kseg*8;
    int vst = vrow*VSTR + vseg*8;

    {
        uint4 kv = *(const uint4*)kgp;
        uint4 vv = *(const uint4*)vgp;
        *(uint4*)(sK  + kst) = kv;
        *(uint4*)(sVt + vst) = vv;
    }
    __syncthreads();

    u32 sKu = (u32)__cvta_generic_to_shared(sK);
    u32 sVu = (u32)__cvta_generic_to_shared(sVt);
    int lmrow = (lane & 7) + ((lane >> 4) << 3);
    int lmhi  = (lane >> 3) & 1;
    int lm_k = lmrow * (KSTR*2) + lmhi * 16;
    int lm_v = lmrow * (VSTR*2) + lmhi * 16;

    for (int kc = 0; kc < 8; kc++) {
        int cur = kc & 1;
        uint4 kvn, vvn;
        if (kc < 7) {
            kvn = *(const uint4*)(kgp + (size_t)(kc+1)*128*HD);
            vvn = *(const uint4*)(vgp + (kc+1)*128);
        }

        u32 ka = sKu + cur*(KBUF*2) + lm_k;
        u32 va = sVu + cur*(VBUF*2) + lm_v;
        #pragma unroll
        for (int sub = 0; sub < 8; sub++) {
            u32 kb0, kb1, kb2, kb3;
            ldsm4(kb0, kb1, kb2, kb3, ka);  ka += 16*(KSTR*2);
            u32 vb0, vb1, vb2, vb3;
            ldsm4(vb0, vb1, vb2, vb3, va);  va += 32;

            float s0[4], s1[4];
            mma16816(s0, qa0,qa1,qa2,qa3, kb0,kb1, 0.f,0.f,0.f,0.f);
            mma16816(s1, qa0,qa1,qa2,qa3, kb2,kb3, 0.f,0.f,0.f,0.f);

            u32 pa0 = bex2(cvt2bf(s0[1], s0[0]));
            u32 pa1 = bex2(cvt2bf(s0[3], s0[2]));
            u32 pa2 = bex2(cvt2bf(s1[1], s1[0]));
            u32 pa3 = bex2(cvt2bf(s1[3], s1[2]));

            mma16816(o0, pa0,pa1,pa2,pa3, vb0,vb1, o0[0],o0[1],o0[2],o0[3]);
            mma16816(o1, pa0,pa1,pa2,pa3, vb2,vb3, o1[0],o1[1],o1[2],o1[3]);
            mma16816(lac, pa0,pa1,pa2,pa3, ONE2, ONE2, lac[0],lac[1],lac[2],lac[3]);
        }

        if (kc < 7) {
            int nb = (kc+1) & 1;
            *(uint4*)(sK  + nb*KBUF + kst) = kvn;
            *(uint4*)(sVt + nb*VBUF + vst) = vvn;
        }
        __syncthreads();
    }

    float ri_lo = 1.0f / lac[0], ri_hi = 1.0f / lac[2];

    __nv_bfloat16* Og = g_ctx + (size_t)bh * TT * HD;
    int rlo = qbase + rq;
    *(u32*)(Og + (size_t)rlo*HD + colq)         = cvt2bf(o0[1]*ri_lo, o0[0]*ri_lo);
    *(u32*)(Og + (size_t)rlo*HD + colq + 8)     = cvt2bf(o1[1]*ri_lo, o1[0]*ri_lo);
    *(u32*)(Og + (size_t)(rlo+8)*HD + colq)     = cvt2bf(o0[3]*ri_hi, o0[2]*ri_hi);
    *(u32*)(Og + (size_t)(rlo+8)*HD + colq + 8) = cvt2bf(o1[3]*ri_hi, o1[2]*ri_hi);
}

// ---------------- K3: MMA output projection + residual + stats + speculative LN ------
__global__ void __launch_bounds__(256) k_outproj(const float* __restrict__ acoustic,
                                                 const float* __restrict__ residual_logit,
                                                 float* __restrict__ out,
                                                 const float* __restrict__ gamma,
                                                 const float* __restrict__ beta) {
    __shared__ __align__(16) __nv_bfloat16 sCtx[128*72];
    __shared__ __align__(16) __nv_bfloat16 sWf[24*72];
    __shared__ __align__(16) float sAc[128*AC];
    __shared__ float sbf[AC], sG[AC], sBt[AC];
    __shared__ float sred[2*AC];
    int tid = threadIdx.x;

    for (int i = tid; i < 216; i += 256)
        ((uint4*)sWf)[i] = ((const uint4*)g_Wfb)[i];
    if (tid < AC) { sbf[tid] = g_bf[tid]; sG[tid] = gamma[tid]; sBt[tid] = beta[tid]; }
    if (tid < 2*AC) sred[tid] = 0.f;

    int tile0 = blockIdx.x * 128;
    int b = tile0 >> 10, t0 = tile0 & 1023;
    {
        int row = tid >> 1, seg = tid & 1;
        #pragma unroll
        for (int h = 0; h < NH; h++) {
            const uint4* src = (const uint4*)(g_ctx + ((size_t)(b*NH+h)*TT + t0) * HD);
            *(uint4*)&sCtx[row*72 + h*16 + seg*8] = src[row*2 + seg];
        }
    }
    {
        const uint4* src = (const uint4*)(acoustic + (size_t)tile0 * AC);
        #pragma unroll
        for (int r = 0; r < 3; r++) {
            int i = r*256 + tid;
            if (i < 640) ((uint4*)sAc)[i] = src[i];
        }
    }
    __syncthreads();

    int lane = tid & 31, w = tid >> 5;
    int rq = lane >> 2, colq = (lane & 3) * 2;
    int r0 = w*16 + rq;

    float d0[4] = {0,0,0,0}, d1[4] = {0,0,0,0}, d2[4] = {0,0,0,0};
    #pragma unroll
    for (int kk = 0; kk < 4; kk++) {
        const __nv_bfloat16* acol = sCtx + kk*16 + colq;
        u32 a0 = *(const u32*)(acol + (size_t)r0*72);
        u32 a1 = *(const u32*)(acol + (size_t)(r0+8)*72);
        u32 a2 = *(const u32*)(acol + (size_t)r0*72 + 8);
        u32 a3 = *(const u32*)(acol + (size_t)(r0+8)*72 + 8);
        const __nv_bfloat16* bcol = sWf + kk*16 + colq;
        u32 b00 = *(const u32*)(bcol + (size_t)rq*72);
        u32 b01 = *(const u32*)(bcol + (size_t)rq*72 + 8);
        u32 b10 = *(const u32*)(bcol + (size_t)(8+rq)*72);
        u32 b11 = *(const u32*)(bcol + (size_t)(8+rq)*72 + 8);
        u32 b20 = *(const u32*)(bcol + (size_t)(16+rq)*72);
        u32 b21 = *(const u32*)(bcol + (size_t)(16+rq)*72 + 8);
        mma16816(d0, a0,a1,a2,a3, b00,b01, d0[0],d0[1],d0[2],d0[3]);
        mma16816(d1, a0,a1,a2,a3, b10,b11, d1[0],d1[1],d1[2],d1[3]);
        mma16816(d2, a0,a1,a2,a3, b20,b21, d2[0],d2[1],d2[2],d2[3]);
    }

    float sig = 1.0f / (1.0f + __expf(-__ldg(residual_logit)));

    float eA[6], eB[6];
    float sumA = 0.f, sumB = 0.f;
    #pragma unroll
    for (int nt = 0; nt < 3; nt++) {
        float* dd = (nt==0) ? d0 : ((nt==1) ? d1 : d2);
        #pragma unroll
        for (int j = 0; j < 2; j++) {
            int c = nt*8 + colq + j;
            float ea = 0.f, eb = 0.f;
            if (c < AC) {
                ea = sAc[r0*AC + c]     + sig * (dd[j]   + sbf[c]);
                eb = sAc[(r0+8)*AC + c] + sig * (dd[2+j] + sbf[c]);
                sumA += ea; sumB += eb;
            }
            eA[nt*2+j] = ea; eB[nt*2+j] = eb;
        }
    }

    #pragma unroll
    for (int q = 0; q < 6; q++) {
        int c = (q>>1)*8 + colq + (q&1);
        float v  = eA[q] + eB[q];
        float vv = eA[q]*eA[q] + eB[q]*eB[q];
        v  += __shfl_xor_sync(0xffffffffu, v,  4);  vv += __shfl_xor_sync(0xffffffffu, vv, 4);
        v  += __shfl_xor_sync(0xffffffffu, v,  8);  vv += __shfl_xor_sync(0xffffffffu, vv, 8);
        v  += __shfl_xor_sync(0xffffffffu, v, 16);  vv += __shfl_xor_sync(0xffffffffu, vv, 16);
        if (lane < 4 && c < AC) {
            atomicAdd(&sred[c],      v);
            atomicAdd(&sred[AC + c], vv);
        }
    }

    float muA = sumA, muB = sumB;
    muA += __shfl_xor_sync(0xffffffffu, muA, 1); muA += __shfl_xor_sync(0xffffffffu, muA, 2);
    muB += __shfl_xor_sync(0xffffffffu, muB, 1); muB += __shfl_xor_sync(0xffffffffu, muB, 2);
    muA *= (1.0f/AC); muB *= (1.0f/AC);
    float varA = 0.f, varB = 0.f;
    #pragma unroll
    for (int q = 0; q < 6; q++) {
        int c = (q>>1)*8 + colq + (q&1);
        if (c < AC) {
            float dA = eA[q] - muA; varA += dA*dA;
            float dB = eB[q] - muB; varB += dB*dB;
        }
    }
    varA += __shfl_xor_sync(0xffffffffu, varA, 1); varA += __shfl_xor_sync(0xffffffffu, varA, 2);
    varB += __shfl_xor_sync(0xffffffffu, varB, 1); varB += __shfl_xor_sync(0xffffffffu, varB, 2);
    float rA = rsqrtf(varA*(1.0f/AC) + 1e-5f);
    float rB = rsqrtf(varB*(1.0f/AC) + 1e-5f);

    size_t tokA = (size_t)(tile0 + r0) * AC;
    size_t tokB = tokA + 8*AC;
    #pragma unroll
    for (int nt = 0; nt < 3; nt++) {
        int c = nt*8 + colq;
        if (c + 1 < AC) {
            float gA0 = sG[c], gA1 = sG[c+1], bb0 = sBt[c], bb1 = sBt[c+1];
            *(float2*)(out + tokA + c) = make_float2((eA[nt*2]-muA)*rA*gA0 + bb0,
                                                     (eA[nt*2+1]-muA)*rA*gA1 + bb1);
            *(float2*)(out + tokB + c) = make_float2((eB[nt*2]-muB)*rB*gA0 + bb0,
                                                     (eB[nt*2+1]-muB)*rB*gA1 + bb1);
            *(float2*)(g_enh + tokA + c) = make_float2(eA[nt*2], eA[nt*2+1]);
            *(float2*)(g_enh + tokB + c) = make_float2(eB[nt*2], eB[nt*2+1]);
        }
    }

    __syncthreads();
    if (tid < 2*AC) g_part_e[blockIdx.x*2*AC + tid] = sred[tid];
}

// ---------------- K4: merged stats-check + fixup (per-block redundant fp32 stats) ----
__global__ void __launch_bounds__(256) k_fixln(float* __restrict__ out,
                                               const float* __restrict__ gamma,
                                               const float* __restrict__ beta) {
    __shared__ float sA[160];
    __shared__ float sE[160];
    __shared__ float s_corr[AC], s_add[AC];
    __shared__ int sflag;
    int tid = threadIdx.x;
    if (tid == 0) sflag = 0;

    if (tid < 160) {
        int idx = tid % 40;
        int q   = tid / 40;
        const float* pa = g_part_a + idx;
        const float* pe = g_part_e + idx;
        int i0 = q * (NRED/4);
        float a0 = 0.f, a1 = 0.f, e0 = 0.f, e1 = 0.f;
        #pragma unroll 4
        for (int i = 0; i < NRED/4; i += 2) {
            a0 += pa[(size_t)(i0 + i)     * 2*AC];
            a1 += pa[(size_t)(i0 + i + 1) * 2*AC];
            e0 += pe[(size_t)(i0 + i)     * 2*AC];
            e1 += pe[(size_t)(i0 + i + 1) * 2*AC];
        }
        sA[tid] = a0 + a1;
        sE[tid] = e0 + e1;
    }
    __syncthreads();

    if (tid < AC) {
        int c = tid;
        float sa = (sA[c]    + sA[40+c])    + (sA[80+c]    + sA[120+c]);
        float qa = (sA[AC+c] + sA[40+AC+c]) + (sA[80+AC+c] + sA[120+AC+c]);
        float se = (sE[c]    + sE[40+c])    + (sE[80+c]    + sE[120+c]);
        float qe = (sE[AC+c] + sE[40+AC+c]) + (sE[80+AC+c] + sE[120+AC+c]);
        const float N = (float)BT;
        float mean = sa / N;
        float va = (qa - sa*sa/N) / (N - 1.0f); if (va < 0.f) va = 0.f;
        float sda = sqrtf(va);
        float ostd = sda + 1e-8f;
        float ve = (qe - se*se/N) / (N - 1.0f); if (ve < 0.f) ve = 0.f;
        float sde = sqrtf(ve);
        float ratio = (sde / ostd) / ((sda / ostd) + 1e-8f);
        float corr = (ratio < 0.4f) ? (0.4f / ratio) : 1.0f;
        s_corr[c] = corr;
        s_add[c]  = mean * (1.0f - corr);
        if (corr != 1.0f) atomicOr(&sflag, 1);
    }
    __syncthreads();
    if (sflag == 0) return;   // speculative LN already correct

    int token = blockIdx.x * 128 + (tid >> 1);
    int cb = (tid & 1) * 10;

    float f[10];
    {
        const float2* p = (const float2*)(g_enh + (size_t)token*AC + cb);
        #pragma unroll
        for (int i = 0; i < 5; i++) { float2 v = p[i]; f[2*i] = v.x; f[2*i+1] = v.y; }
    }
    float mu = 0.f;
    #pragma unroll
    for (int ci = 0; ci < 10; ci++) {
        f[ci] = f[ci] * s_corr[cb+ci] + s_add[cb+ci];
        mu += f[ci];
    }
    mu += __shfl_xor_sync(0xffffffffu, mu, 1);
    mu *= (1.0f / AC);
    float var = 0.f;
    #pragma unroll
    for (int ci = 0; ci < 10; ci++) { float d = f[ci] - mu; var += d * d; }
    var += __shfl_xor_sync(0xffffffffu, var, 1);
    var *= (1.0f / AC);
    float r = rsqrtf(var + 1e-5f);

    float o[10];
    #pragma unroll
    for (int ci = 0; ci < 10; ci++)
        o[ci] = (f[ci] - mu) * r * __ldg(&gamma[cb+ci]) + __ldg(&beta[cb+ci]);
    float2* dst = (float2*)(out + (size_t)token*AC + cb);
    #pragma unroll
    for (int i = 0; i < 5; i++) dst[i] = make_float2(o[2*i], o[2*i+1]);
}

// ---------------- launcher ----------------
extern "C" void kernel_launch(void* const* d_in, const int* in_sizes, int n_in,
                              void* d_out, int out_size) {
    (void)in_sizes; (void)n_in; (void)out_size;
    const float* acoustic = (const float*)d_in[0];
    const float* semantic = (const float*)d_in[1];
    const float* Wq       = (const float*)d_in[2];
    const float* bq       = (const float*)d_in[3];
    const float* Wkv      = (const float*)d_in[4];
    const float* bkv      = (const float*)d_in[5];
    const float* in_w     = (const float*)d_in[6];
    const float* in_b     = (const float*)d_in[7];
    const float* out_w    = (const float*)d_in[8];
    const float* out_b    = (const float*)d_in[9];
    const float* proj_w   = (const float*)d_in[10];
    const float* proj_b   = (const float*)d_in[11];
    const float* rl       = (const float*)d_in[12];
    const float* gamma    = (const float*)d_in[13];
    const float* beta     = (const float*)d_in[14];
    float* out = (float*)d_out;

    k_fuse<<<64, 128>>>(Wq, bq, Wkv, bkv, in_w, in_b, out_w, out_b, proj_w, proj_b);
    k_qkv<<<NRED, 128>>>(semantic, acoustic);                  // launch 1
    dim3 ga(TT/128, NH, BB);
    k_attn<<<ga, 256>>>();                                     // launch 2
    k_outproj<<<NRED, 256>>>(acoustic, rl, out, gamma, beta);  // launch 3 <- captured
    k_fixln<<<256, 256>>>(out, gamma, beta);                   // launch 4
}